// round 4
// baseline (speedup 1.0000x reference)
#include <cuda_runtime.h>

// ---------------------------------------------------------------------------
// 2-layer LSTM (B=8, T=2048, D_IN=256, H=512), relu cell nonlinearity.
// Two fused persistent groups, 64 blocks each (1 block/SM, all resident):
//   G0: h0[t] = cell(W0 x[t] + U0 h0[t-1] + b)        k=768
//   G1: h2[t] = cell(W1 h0[t] + U1 h2[t-1] + b)       k=1024  -> output
// Sync: h values published as tagged u64 {epoch<<32 | f32} to L2 ring
// buffers (depth 8); consumers spin directly on the data words (single L2
// hop). One lazy counter (G1 staging progress) gates G0 ring wrap-around.
// Weights in SMEM (pad-33, conflict-free); inner loop = packed fma.rn.f32x2.
// ---------------------------------------------------------------------------

typedef unsigned long long u64;
typedef unsigned u32;

#define TSTEPS 2048
#define HID    512
#define BATCH  8
#define DIN    256
#define DEPTH  8
#define NB_G   64
#define NBLK   128
#define NTHR   512

#define OUT_HH (BATCH * TSTEPS * HID)            // 8388608
#define OUT_CC (OUT_HH + 2 * BATCH * HID)        // 8396800

// SMEM float offsets (sized for G1: KLEN=1024)
#define W_OFF     0
#define IN_OFF    (1024 * 33)                    // 33792
#define PART_OFF  (IN_OFF + 1024 * 8)            // 41984
#define GATES_OFF (PART_OFF + 32 * 32 * 9)       // 51200
#define C_OFF     (GATES_OFF + 256)              // 51456
#define SM_FLOATS (C_OFF + 64)                   // 51520
#define SM_BYTES  (SM_FLOATS * 4)                // 206080

__device__ u32 g_cnt1;                           // G1 staging progress
__device__ u64 g_h0ring[DEPTH * HID * BATCH];    // [slot][j*8+b] tagged
__device__ u64 g_h2ring[DEPTH * HID * BATCH];

__global__ void init_kernel() {
    u32 i = blockIdx.x * blockDim.x + threadIdx.x;
    if (i == 0) g_cnt1 = 0;
    for (u32 k = i; k < DEPTH * HID * BATCH; k += gridDim.x * blockDim.x) {
        g_h0ring[k] = 0ull;
        g_h2ring[k] = 0ull;
    }
}

__device__ __forceinline__ u64 packdup(float w) {
    u64 r;
    asm("mov.b64 %0, {%1, %1};" : "=l"(r) : "f"(w));
    return r;
}
__device__ __forceinline__ void ffma2(u64& d, u64 a, u64 b) {
    asm("fma.rn.f32x2 %0, %1, %2, %3;" : "=l"(d) : "l"(a), "l"(b), "l"(d));
}
__device__ __forceinline__ u64 add2(u64 a, u64 b) {
    u64 d;
    asm("add.rn.f32x2 %0, %1, %2;" : "=l"(d) : "l"(a), "l"(b));
    return d;
}
__device__ __forceinline__ float2 unpk(u64 v) {
    float2 f;
    asm("mov.b64 {%0, %1}, %2;" : "=f"(f.x), "=f"(f.y) : "l"(v));
    return f;
}
__device__ __forceinline__ u32 ld_acquire(const u32* p) {
    u32 v;
    asm volatile("ld.acquire.gpu.global.u32 %0, [%1];" : "=r"(v) : "l"(p) : "memory");
    return v;
}
__device__ __forceinline__ void red_release(u32* p) {
    asm volatile("red.release.gpu.global.add.u32 [%0], 1;" :: "l"(p) : "memory");
}
__device__ __forceinline__ float sigmoidf_(float x) {
    return 1.0f / (1.0f + __expf(-x));
}

// spin until all 8 tagged words carry `exp`, then deposit values at dst[0..7]
__device__ __forceinline__ void stage_h(const u64* __restrict__ src, u32 exp,
                                        float* __restrict__ dst) {
    u64 v[8];
    #pragma unroll
    for (int p = 0; p < 8; ++p) v[p] = __ldcv(src + p);
    for (;;) {
        bool bad = false;
        #pragma unroll
        for (int p = 0; p < 8; ++p)
            if ((u32)(v[p] >> 32) != exp) { bad = true; v[p] = __ldcv(src + p); }
        if (!bad) break;
    }
    #pragma unroll
    for (int p = 0; p < 8; ++p) dst[p] = __uint_as_float((u32)v[p]);
}
__device__ __forceinline__ void publish(u64* dst, float h, u32 tag) {
    __stcg(dst, ((u64)tag << 32) | (u64)__float_as_uint(h));
}

// GRP 0: layer-0 fused (k = 256 x + 512 h0) ; GRP 1: layer-1 fused (512 h0 + 512 h2)
template <int GRP>
__device__ __forceinline__ void run_group(
    const float* __restrict__ x,
    const float* __restrict__ wW, const float* __restrict__ wb,
    const float* __restrict__ uW, const float* __restrict__ ub_,
    float* __restrict__ out, float* sm, int blk, int tid)
{
    constexpr int KLEN  = (GRP == 0) ? 768 : 1024;
    constexpr int SPLIT = (GRP == 0) ? 256 : 512;    // wW column count
    constexpr int KW    = KLEN / 16;                 // k per warp (48 | 64)
    constexpr int NKK   = KW / 4;                    // 12 | 16

    float* W_s     = sm + W_OFF;      // [k][33] pad, col = local row
    float* in_s    = sm + IN_OFF;     // [k][8]
    float* part_s  = sm + PART_OFF;   // [slice(32)][row(32) stride 9]
    float* gates_s = sm + GATES_OFF;  // [rl*8+b]
    float* c_s     = sm + C_OFF;      // [u*8+b]

    const int jb = blk * 8;           // unit base (8 units/block)

    // ---- one-time: weights (transposed, padded) + bias + cell init ----
    for (int idx = tid; idx < 32 * KLEN; idx += NTHR) {
        int rl = idx / KLEN, k = idx - rl * KLEN;
        int gid = (rl >> 3) * HID + jb + (rl & 7);
        float v = (k < SPLIT) ? wW[(size_t)gid * SPLIT + k]
                              : uW[(size_t)gid * HID + (k - SPLIT)];
        W_s[k * 33 + rl] = v;
    }
    float biasv = 0.0f;
    if (tid < 256) {
        int rl = tid >> 3;
        int gid = (rl >> 3) * HID + jb + (rl & 7);
        biasv = wb[gid] + ub_[gid];
    }
    if (tid < 64) c_s[tid] = 0.0f;
    __syncthreads();

    const int warp  = tid >> 5, lane = tid & 31;
    const int khalf = lane >> 3, rg = lane & 7, rl0 = rg * 4;
    const int kw0   = warp * KW + khalf;   // k = kw0 + kk*4

    for (int t = 0; t < TSTEPS; ++t) {
        const int slot = t & 7, pslot = (t - 1) & 7;

        // ---- stage inputs (spin directly on tagged data) ----
        if (GRP == 0) {
            int b = tid >> 6, d4 = (tid & 63) * 4;
            float4 v = __ldcg((const float4*)&x[((size_t)b * TSTEPS + t) * DIN + d4]);
            in_s[(d4 + 0) * 8 + b] = v.x;
            in_s[(d4 + 1) * 8 + b] = v.y;
            in_s[(d4 + 2) * 8 + b] = v.z;
            in_s[(d4 + 3) * 8 + b] = v.w;
            stage_h(g_h0ring + pslot * 4096 + tid * 8, (u32)t, &in_s[(256 + tid) * 8]);
        } else {
            stage_h(g_h0ring + slot * 4096 + tid * 8, (u32)(t + 1), &in_s[tid * 8]);
            stage_h(g_h2ring + pslot * 4096 + tid * 8, (u32)t, &in_s[(512 + tid) * 8]);
        }
        __syncthreads();
        if (GRP == 1) {
            if (tid == 0) red_release(&g_cnt1);   // "this block staged step t"
        } else if (tid == 0 && t >= DEPTH) {
            // gate h0 ring wrap: all G1 blocks must have staged step t-8
            u32 thr = (u32)(NB_G * (t - 7));
            while (ld_acquire(&g_cnt1) < thr) __nanosleep(64);
        }

        // ---- dot products: 4 rows x (KW/4) k x 8 batch per thread ----
        u64 a0[4], a1[4], a2[4], a3[4];
        #pragma unroll
        for (int p = 0; p < 4; ++p) { a0[p] = 0; a1[p] = 0; a2[p] = 0; a3[p] = 0; }

        const float* wp = W_s + kw0 * 33 + rl0;
        const float* ip = in_s + kw0 * 8;
        #pragma unroll
        for (int kk = 0; kk < NKK; ++kk) {
            float w0 = wp[0], w1 = wp[1], w2 = wp[2], w3 = wp[3];
            u64 i0 = *(const u64*)(ip + 0);
            u64 i1 = *(const u64*)(ip + 2);
            u64 i2 = *(const u64*)(ip + 4);
            u64 i3 = *(const u64*)(ip + 6);
            u64 d0 = packdup(w0), d1 = packdup(w1), d2 = packdup(w2), d3 = packdup(w3);
            ffma2(a0[0], d0, i0); ffma2(a0[1], d0, i1);
            ffma2(a0[2], d0, i2); ffma2(a0[3], d0, i3);
            ffma2(a1[0], d1, i0); ffma2(a1[1], d1, i1);
            ffma2(a1[2], d1, i2); ffma2(a1[3], d1, i3);
            ffma2(a2[0], d2, i0); ffma2(a2[1], d2, i1);
            ffma2(a2[2], d2, i2); ffma2(a2[3], d2, i3);
            ffma2(a3[0], d3, i0); ffma2(a3[1], d3, i1);
            ffma2(a3[2], d3, i2); ffma2(a3[3], d3, i3);
            wp += 4 * 33;
            ip += 4 * 8;
        }

        // ---- one shfl round (khalf pairs), then write 32-slice partials ----
        #pragma unroll
        for (int p = 0; p < 4; ++p) {
            a0[p] = add2(a0[p], __shfl_xor_sync(0xFFFFFFFFu, a0[p], 8));
            a1[p] = add2(a1[p], __shfl_xor_sync(0xFFFFFFFFu, a1[p], 8));
            a2[p] = add2(a2[p], __shfl_xor_sync(0xFFFFFFFFu, a2[p], 8));
            a3[p] = add2(a3[p], __shfl_xor_sync(0xFFFFFFFFu, a3[p], 8));
        }
        if ((khalf & 1) == 0) {
            int s2 = warp * 2 + (khalf >> 1);     // 0..31
            #pragma unroll
            for (int p = 0; p < 4; ++p) {
                float2 f0 = unpk(a0[p]), f1 = unpk(a1[p]);
                float2 f2 = unpk(a2[p]), f3 = unpk(a3[p]);
                float* q = &part_s[(s2 * 32 + rl0) * 9];
                q[2 * p] = f0.x; q[2 * p + 1] = f0.y;
                q[9 + 2 * p] = f1.x; q[9 + 2 * p + 1] = f1.y;
                q[18 + 2 * p] = f2.x; q[18 + 2 * p + 1] = f2.y;
                q[27 + 2 * p] = f3.x; q[27 + 2 * p + 1] = f3.y;
            }
        }
        __syncthreads();

        // ---- final reduce across 32 slices ----
        if (tid < 256) {
            int rl = tid >> 3, b = tid & 7;
            float s = biasv;
            #pragma unroll
            for (int w = 0; w < 32; ++w)
                s += part_s[(w * 32 + rl) * 9 + b];
            gates_s[tid] = s;
        }
        __syncthreads();

        // ---- pointwise cell + publish ----
        if (tid < 64) {
            float iv = sigmoidf_(gates_s[tid]);
            float fv = sigmoidf_(gates_s[64 + tid]);
            float gv = tanhf(gates_s[128 + tid]);
            float ov = sigmoidf_(gates_s[192 + tid]);
            float c = fv * c_s[tid] + iv * gv;
            c_s[tid] = c;
            float h = ov * fmaxf(c, 0.0f);
            int u = tid >> 3, b = tid & 7, j = jb + u;
            u64* ring = (GRP == 0) ? g_h0ring : g_h2ring;
            publish(&ring[slot * 4096 + j * 8 + b], h, (u32)(t + 1));
            if (GRP == 1)
                out[((size_t)b * TSTEPS + t) * HID + j] = h;
            if (t == TSTEPS - 1) {
                out[OUT_HH + GRP * BATCH * HID + b * HID + j] = h;
                out[OUT_CC + GRP * BATCH * HID + b * HID + j] = c;
            }
        }
        // next iteration's stage barrier orders in_s reuse
    }
}

extern __shared__ float smem_dyn[];

__global__ void __launch_bounds__(NTHR, 1)
lstm2_kernel(const float* __restrict__ x,
             const float* __restrict__ w0w, const float* __restrict__ w0b,
             const float* __restrict__ u0w, const float* __restrict__ u0b,
             const float* __restrict__ w1w, const float* __restrict__ w1b,
             const float* __restrict__ u1w, const float* __restrict__ u1b,
             float* __restrict__ out)
{
    const int tid = threadIdx.x, bx = blockIdx.x;
    if (bx < NB_G)
        run_group<0>(x, w0w, w0b, u0w, u0b, out, smem_dyn, bx, tid);
    else
        run_group<1>(x, w1w, w1b, u1w, u1b, out, smem_dyn, bx - NB_G, tid);
}

extern "C" void kernel_launch(void* const* d_in, const int* in_sizes, int n_in,
                              void* d_out, int out_size)
{
    (void)in_sizes; (void)n_in; (void)out_size;
    static int attr_done = 0;
    if (!attr_done) {
        cudaFuncSetAttribute(lstm2_kernel,
                             cudaFuncAttributeMaxDynamicSharedMemorySize, SM_BYTES);
        attr_done = 1;
        (void)cudaGetLastError();
    }

    const float* x   = (const float*)d_in[0];
    const float* w0w = (const float*)d_in[1];
    const float* w0b = (const float*)d_in[2];
    const float* u0w = (const float*)d_in[3];
    const float* u0b = (const float*)d_in[4];
    const float* w1w = (const float*)d_in[5];
    const float* w1b = (const float*)d_in[6];
    const float* u1w = (const float*)d_in[7];
    const float* u1b = (const float*)d_in[8];
    float* out = (float*)d_out;

    init_kernel<<<128, 256>>>();
    lstm2_kernel<<<NBLK, NTHR, SM_BYTES>>>(x, w0w, w0b, u0w, u0b,
                                           w1w, w1b, u1w, u1b, out);
}

// round 16
// speedup vs baseline: 2.1195x; 2.1195x over previous
#include <cuda_runtime.h>

// ---------------------------------------------------------------------------
// 2-layer LSTM (B=8, T=2048, D_IN=256, H=512), relu cell nonlinearity.
// 4-group pipelined persistent design (R3 architecture, PROVEN PASSING):
//   G2 (16 blk): wx0[t] = W0 x[t] + b0   (no deps, streams ahead)
//   G0 (32 blk): h0[t]  = cell(wx0[t] + U0 h0[t-1])
//   G3 (32 blk): wx1[t] = W1 h0[t] + b1  (1 step behind G0)
//   G1 (32 blk): h2[t]  = cell(wx1[t] + U1 h2[t-1])  -> output
// Weights persist in REGISTERS (4 rows x 16 k per thread). Ring buffers in
// L2 (__device__ arrays, depth 8). Per-group monotonic counters with
// red.release / ld.acquire.
// R14 change vs R3: BOUNDED hot spin in dependency polls — hot for 4096
// iters (fast detect), then __nanosleep(64) fallback (container-safe;
// unbounded hot spins correlate with container hangs, R1/R13).
// ---------------------------------------------------------------------------

typedef unsigned long long u64;
typedef unsigned u32;

#define TSTEPS 2048
#define HID    512
#define BATCH  8
#define DIN    256
#define DEPTH  8

#define NB_G2 16
#define NB_G0 32
#define NB_G3 32
#define NB_G1 32
#define NBLK  112
#define NTHR  512

#define OUT_HH (BATCH * TSTEPS * HID)
#define OUT_CC (OUT_HH + 2 * BATCH * HID)

// SMEM float offsets
#define IN_OFF    0
#define PART_OFF  4096
#define GATES_OFF (4096 + 10240)
#define C_OFF     (GATES_OFF + 1024)
#define SM_FLOATS (C_OFF + 128)
#define SM_BYTES  (SM_FLOATS * 4)

// counters: 0=G2, 1=G0, 2=G3, 3=G1
__device__ u32   g_cnt[4];
__device__ float g_h0ring[DEPTH * HID * BATCH];
__device__ float g_h2ring[DEPTH * HID * BATCH];
__device__ float g_wx0ring[DEPTH * 4 * HID * BATCH];
__device__ float g_wx1ring[DEPTH * 4 * HID * BATCH];

__global__ void init_kernel() {
    int i = blockIdx.x * blockDim.x + threadIdx.x;
    if (i < 4) g_cnt[i] = 0;
    for (int k = i; k < DEPTH * HID * BATCH; k += gridDim.x * blockDim.x) {
        g_h0ring[k] = 0.0f;
        g_h2ring[k] = 0.0f;
    }
}

__device__ __forceinline__ u64 packdup(float w) {
    u64 r;
    asm("mov.b64 %0, {%1, %1};" : "=l"(r) : "f"(w));
    return r;
}
__device__ __forceinline__ void ffma2(u64& d, u64 a, u64 b) {
    asm("fma.rn.f32x2 %0, %1, %2, %3;" : "=l"(d) : "l"(a), "l"(b), "l"(d));
}
__device__ __forceinline__ u64 add2(u64 a, u64 b) {
    u64 d;
    asm("add.rn.f32x2 %0, %1, %2;" : "=l"(d) : "l"(a), "l"(b));
    return d;
}
__device__ __forceinline__ float2 unpk(u64 v) {
    float2 f;
    asm("mov.b64 {%0, %1}, %2;" : "=f"(f.x), "=f"(f.y) : "l"(v));
    return f;
}
__device__ __forceinline__ u32 ld_acquire(const u32* p) {
    u32 v;
    asm volatile("ld.acquire.gpu.global.u32 %0, [%1];" : "=r"(v) : "l"(p) : "memory");
    return v;
}
__device__ __forceinline__ void red_release(u32* p) {
    asm volatile("red.release.gpu.global.add.u32 [%0], 1;" :: "l"(p) : "memory");
}
__device__ __forceinline__ float sigmoidf_(float x) {
    return 1.0f / (1.0f + __expf(-x));
}
// bounded hot spin: fast detect, nanosleep fallback for safety
__device__ __forceinline__ void poll_counter(const u32* p, u32 thr) {
    int spins = 0;
    while (ld_acquire(p) < thr) {
        if (++spins > 4096) __nanosleep(64);
    }
}

// GRP: 0=wx0 proj (128 rows, k=256), 1=rec L0 (64 rows, k=512),
//      2=wx1 proj (64 rows, k=512), 3=rec L1 (64 rows, k=512)
template <int GRP>
__device__ __forceinline__ void run_group(
    const float* __restrict__ x,
    const float* __restrict__ W,
    const float* __restrict__ bA, const float* __restrict__ bB,
    float* __restrict__ out,
    float* __restrict__ sm, int blk, int tid)
{
    constexpr bool ISREC  = (GRP == 1) || (GRP == 3);
    constexpr int  NROWS  = (GRP == 0) ? 128 : 64;
    constexpr int  KLEN   = (GRP == 0) ? 256 : 512;
    constexpr int  UNITS  = NROWS / 4;
    constexpr int  NSLICE = KLEN / 32;
    constexpr int  NE     = (GRP == 0) ? 2 : 1;     // reduce entries per thread

    float* in_s    = sm + IN_OFF;     // [k][8b]
    float* part_s  = sm + PART_OFF;   // [warp][row][b]
    float* gates_s = sm + GATES_OFF;  // [g*64 + u*8 + b]
    float* c_s     = sm + C_OFF;      // [unit][b]

    const int ub     = blk * UNITS;
    const int warp   = tid >> 5;
    const int lane   = tid & 31;
    const int kslice = warp % NSLICE;
    const int rowset = warp / NSLICE;
    const int rowgrp = lane & 15;
    const int khalf  = lane >> 4;
    const int kbase  = kslice * 32 + khalf * 16;
    const int rl0    = rowset * 64 + rowgrp * 4;

    // ---- one-time: weights into registers (4 rows x 16 k) ----
    float wreg[4][16];
    #pragma unroll
    for (int r = 0; r < 4; ++r) {
        int rl  = rl0 + r;
        int gid = (rl / UNITS) * HID + ub + (rl % UNITS);
        #pragma unroll
        for (int kk = 0; kk < 16; ++kk)
            wreg[r][kk] = __ldg(&W[(size_t)gid * KLEN + kbase + kk]);
    }

    // ---- one-time: bias (proj) preload for the reduce thread(s) ----
    float biasv[NE];
    if (!ISREC) {
        #pragma unroll
        for (int e = 0; e < NE; ++e) {
            int idx = tid + e * 512;
            int rl  = idx >> 3;
            int gid = (rl / UNITS) * HID + ub + (rl % UNITS);
            biasv[e] = __ldg(&bA[gid]) + __ldg(&bB[gid]);
        }
    }
    if (ISREC && tid < 128) c_s[tid] = 0.0f;
    __syncthreads();

    for (int t = 0; t < TSTEPS; ++t) {
        const int slot = t & (DEPTH - 1);

        // ---- poll dependencies (threads 0..2 in parallel, bounded hot spin) ----
        int cidx[3] = {0, 0, 0};
        u32 cthr[3] = {0, 0, 0};
        if (GRP == 0) {
            if (t >= DEPTH) { cidx[0] = 1; cthr[0] = NB_G0 * (u32)(t - DEPTH + 1); }
        } else if (GRP == 1) {
            cidx[0] = 0; cthr[0] = NB_G2 * (u32)(t + 1);
            if (t >= 1)     { cidx[1] = 1; cthr[1] = NB_G0 * (u32)t; }
            if (t >= DEPTH) { cidx[2] = 2; cthr[2] = NB_G3 * (u32)(t - DEPTH + 1); }
        } else if (GRP == 2) {
            cidx[0] = 1; cthr[0] = NB_G0 * (u32)(t + 1);
            if (t >= DEPTH) { cidx[1] = 3; cthr[1] = NB_G1 * (u32)(t - DEPTH + 1); }
        } else {
            cidx[0] = 2; cthr[0] = NB_G3 * (u32)(t + 1);
            if (t >= 1) { cidx[1] = 3; cthr[1] = NB_G1 * (u32)t; }
        }
        if (tid < 3 && cthr[tid] > 0) {
            poll_counter(&g_cnt[cidx[tid]], cthr[tid]);
        }
        __syncthreads();

        // ---- stage step input into in_s[k][b] ----
        if (GRP == 0) {
            int b = tid >> 6, k4 = (tid & 63) * 4;
            const float4 v = __ldcg((const float4*)&x[((size_t)b * TSTEPS + t) * DIN + k4]);
            in_s[(k4 + 0) * 8 + b] = v.x;
            in_s[(k4 + 1) * 8 + b] = v.y;
            in_s[(k4 + 2) * 8 + b] = v.z;
            in_s[(k4 + 3) * 8 + b] = v.w;
        } else {
            const float* ring = (GRP == 3) ? g_h2ring : g_h0ring;
            const int rslot = (GRP == 2) ? slot : ((t + DEPTH - 1) & (DEPTH - 1));
            const float* src = ring + rslot * HID * BATCH + tid * 8;
            float4 a = __ldcg((const float4*)src);
            float4 b = __ldcg((const float4*)(src + 4));
            *(float4*)&in_s[tid * 8]     = a;
            *(float4*)&in_s[tid * 8 + 4] = b;
        }

        // ---- prefetch wx value for the reduce thread (recurrence only) ----
        float addv = 0.0f;
        if (ISREC) {
            int rl = tid >> 3, b = tid & 7;
            int gid = (rl >> 4) * HID + ub + (rl & 15);
            const float* wxr = (GRP == 1) ? g_wx0ring : g_wx1ring;
            addv = __ldcg(&wxr[slot * 4 * HID * BATCH + gid * 8 + b]);
        }
        __syncthreads();

        // ---- inner dot: 4 rows x 16 k x 8 batch per thread ----
        u64 acc[4][4];
        #pragma unroll
        for (int r = 0; r < 4; ++r)
            #pragma unroll
            for (int p = 0; p < 4; ++p) acc[r][p] = 0;

        #pragma unroll
        for (int kk = 0; kk < 16; ++kk) {
            const float* ip = &in_s[(kbase + kk) * 8];
            u64 i0 = *(const u64*)(ip + 0);
            u64 i1 = *(const u64*)(ip + 2);
            u64 i2 = *(const u64*)(ip + 4);
            u64 i3 = *(const u64*)(ip + 6);
            #pragma unroll
            for (int r = 0; r < 4; ++r) {
                u64 w2 = packdup(wreg[r][kk]);
                ffma2(acc[r][0], w2, i0);
                ffma2(acc[r][1], w2, i1);
                ffma2(acc[r][2], w2, i2);
                ffma2(acc[r][3], w2, i3);
            }
        }

        // ---- khalf pair reduce + write partials ----
        #pragma unroll
        for (int r = 0; r < 4; ++r)
            #pragma unroll
            for (int p = 0; p < 4; ++p) {
                u64 o = __shfl_xor_sync(0xFFFFFFFFu, acc[r][p], 16);
                acc[r][p] = add2(acc[r][p], o);
            }
        if (khalf == 0) {
            #pragma unroll
            for (int r = 0; r < 4; ++r) {
                float* pp = &part_s[kslice * NROWS * 10 + (rl0 + r) * 10];
                #pragma unroll
                for (int p = 0; p < 4; ++p)
                    *(float2*)(pp + 2 * p) = unpk(acc[r][p]);
            }
        }
        __syncthreads();

        // ---- final reduce across k-slices ----
        #pragma unroll
        for (int e = 0; e < NE; ++e) {
            int idx = tid + e * 512;
            int rl = idx >> 3, b = idx & 7;
            float s = ISREC ? addv : biasv[e];
            #pragma unroll
            for (int w = 0; w < NSLICE; ++w)
                s += part_s[w * NROWS * 10 + rl * 10 + b];
            if (ISREC) {
                gates_s[idx] = s;
            } else {
                int gid = (rl / UNITS) * HID + ub + (rl % UNITS);
                float* wxr = (GRP == 0) ? g_wx0ring : g_wx1ring;
                __stcg(&wxr[slot * 4 * HID * BATCH + gid * 8 + b], s);
            }
        }

        // ---- pointwise LSTM cell (recurrence groups) ----
        if (ISREC) {
            __syncthreads();
            if (tid < UNITS * 8) {   // 128
                float iv = sigmoidf_(gates_s[tid]);
                float fv = sigmoidf_(gates_s[128 + tid]);
                float gv = tanhf(gates_s[256 + tid]);
                float ov = sigmoidf_(gates_s[384 + tid]);
                float c = fv * c_s[tid] + iv * gv;
                c_s[tid] = c;
                float h = ov * fmaxf(c, 0.0f);
                int u = tid >> 3, b = tid & 7, j = ub + u;
                float* hr = (GRP == 1) ? g_h0ring : g_h2ring;
                __stcg(&hr[slot * HID * BATCH + j * 8 + b], h);
                if (GRP == 3)
                    out[((size_t)b * TSTEPS + t) * HID + j] = h;
                if (t == TSTEPS - 1) {
                    int L = (GRP == 1) ? 0 : 1;
                    out[OUT_HH + L * BATCH * HID + b * HID + j] = h;
                    out[OUT_CC + L * BATCH * HID + b * HID + j] = c;
                }
            }
        }

        __syncthreads();
        if (tid == 0) red_release(&g_cnt[GRP]);
    }
}

extern __shared__ float smem_dyn[];

__global__ void __launch_bounds__(NTHR, 1)
lstm4_kernel(const float* __restrict__ x,
             const float* __restrict__ w0w, const float* __restrict__ w0b,
             const float* __restrict__ u0w, const float* __restrict__ u0b,
             const float* __restrict__ w1w, const float* __restrict__ w1b,
             const float* __restrict__ u1w, const float* __restrict__ u1b,
             float* __restrict__ out)
{
    const int tid = threadIdx.x;
    const int bx  = blockIdx.x;
    if (bx < NB_G2)
        run_group<0>(x, w0w, w0b, u0b, out, smem_dyn, bx, tid);
    else if (bx < NB_G2 + NB_G0)
        run_group<1>(x, u0w, nullptr, nullptr, out, smem_dyn, bx - NB_G2, tid);
    else if (bx < NB_G2 + NB_G0 + NB_G3)
        run_group<2>(x, w1w, w1b, u1b, out, smem_dyn, bx - NB_G2 - NB_G0, tid);
    else
        run_group<3>(x, u1w, nullptr, nullptr, out, smem_dyn,
                     bx - NB_G2 - NB_G0 - NB_G3, tid);
}

extern "C" void kernel_launch(void* const* d_in, const int* in_sizes, int n_in,
                              void* d_out, int out_size)
{
    (void)in_sizes; (void)n_in; (void)out_size;
    static int attr_done = 0;
    if (!attr_done) {
        cudaFuncSetAttribute(lstm4_kernel,
                             cudaFuncAttributeMaxDynamicSharedMemorySize, SM_BYTES);
        attr_done = 1;
        (void)cudaGetLastError();
    }

    const float* x   = (const float*)d_in[0];
    const float* w0w = (const float*)d_in[1];
    const float* w0b = (const float*)d_in[2];
    const float* u0w = (const float*)d_in[3];
    const float* u0b = (const float*)d_in[4];
    const float* w1w = (const float*)d_in[5];
    const float* w1b = (const float*)d_in[6];
    const float* u1w = (const float*)d_in[7];
    const float* u1b = (const float*)d_in[8];
    float* out = (float*)d_out;

    init_kernel<<<64, 256>>>();
    lstm4_kernel<<<NBLK, NTHR, SM_BYTES>>>(x, w0w, w0b, u0w, u0b,
                                           w1w, w1b, u1w, u1b, out);
}